// round 13
// baseline (speedup 1.0000x reference)
#include <cuda_runtime.h>
#include <cuda_fp16.h>
#include <math.h>
#include <stdint.h>

#define D_MODEL 1024
#define NHEADS  16
#define DK      64
#define BB      2
#define TT      2048
#define MTOT    (BB*TT)   // 4096 rows

// ---------------- scratch (static device arrays; no allocation allowed) ----
__device__ __half g_Qr[MTOT*D_MODEL];    // RoPE'd Q, pre-scaled by 0.125*log2(e)
__device__ __half g_Kr[MTOT*D_MODEL];    // RoPE'd K (fp16)
__device__ __half g_Vt[MTOT*D_MODEL];    // V transposed [b,h,d,t] (fp16)
__device__ __half g_Attn[MTOT*D_MODEL];  // attention output (fp16)
__device__ __half g_Xh[MTOT*D_MODEL];    // input x (fp16)
__device__ __half g_Wqh[D_MODEL*D_MODEL];
__device__ __half g_Wkh[D_MODEL*D_MODEL];
__device__ __half g_Woh[D_MODEL*D_MODEL];
__device__ float  g_cos[TT*32];
__device__ float  g_sin[TT*32];

#define EXP_SCALE 0.180336880111120405f   // 0.125 * log2(e), folded into Q

// ---------------- helpers ---------------------------------------------------
__device__ __forceinline__ void mma16(float4& c,
    uint32_t a0, uint32_t a1, uint32_t a2, uint32_t a3,
    uint32_t b0, uint32_t b1)
{
    asm volatile(
        "mma.sync.aligned.m16n8k16.row.col.f32.f16.f16.f32 "
        "{%0,%1,%2,%3}, {%4,%5,%6,%7}, {%8,%9}, {%0,%1,%2,%3};\n"
        : "+f"(c.x), "+f"(c.y), "+f"(c.z), "+f"(c.w)
        : "r"(a0), "r"(a1), "r"(a2), "r"(a3), "r"(b0), "r"(b1));
}

__device__ __forceinline__ void ldsm4(uint32_t& r0, uint32_t& r1,
                                      uint32_t& r2, uint32_t& r3, uint32_t addr)
{
    asm volatile("ldmatrix.sync.aligned.m8n8.x4.shared.b16 {%0,%1,%2,%3}, [%4];"
                 : "=r"(r0), "=r"(r1), "=r"(r2), "=r"(r3) : "r"(addr));
}

__device__ __forceinline__ uint32_t s2u(const void* p)
{
    return (uint32_t)__cvta_generic_to_shared(p);
}

__device__ __forceinline__ void cpa16(uint32_t dst, const void* src)
{
    asm volatile("cp.async.cg.shared.global [%0], [%1], 16;" :: "r"(dst), "l"(src));
}
#define CP_COMMIT() asm volatile("cp.async.commit_group;" ::: "memory")
#define CP_WAIT1()  asm volatile("cp.async.wait_group 1;" ::: "memory")

__device__ __forceinline__ uint32_t pack_h2(float x, float y)
{
    __half2 h = __floats2half2_rn(x, y);
    return *(uint32_t*)&h;
}

__device__ __forceinline__ uint32_t h2ex2(uint32_t u)
{
    uint32_t r;
    asm("ex2.approx.f16x2 %0, %1;" : "=r"(r) : "r"(u));
    return r;
}

// ---------------- prepass: fused f32 -> f16 for x, Wq, Wk, Wo ----------------
#define NX8 (MTOT*D_MODEL/8)       // 524288
#define NW8 (D_MODEL*D_MODEL/8)    // 131072
#define NALL8 (NX8 + 3*NW8)        // 917504

__global__ void f2h_all_kernel(const float4* __restrict__ x,
                               const float4* __restrict__ wq,
                               const float4* __restrict__ wk,
                               const float4* __restrict__ wo)
{
    int i = blockIdx.x * blockDim.x + threadIdx.x;
    if (i >= NALL8) return;
    const float4* src;
    uint4* dst;
    int j;
    if (i < NX8)               { src = x;  dst = (uint4*)g_Xh;  j = i; }
    else if (i < NX8 + NW8)    { src = wq; dst = (uint4*)g_Wqh; j = i - NX8; }
    else if (i < NX8 + 2*NW8)  { src = wk; dst = (uint4*)g_Wkh; j = i - NX8 - NW8; }
    else                       { src = wo; dst = (uint4*)g_Woh; j = i - NX8 - 2*NW8; }
    float4 a = src[2*j], b = src[2*j+1];
    union { uint4 u; __half2 h[4]; } p;
    p.h[0] = __floats2half2_rn(a.x, a.y);
    p.h[1] = __floats2half2_rn(a.z, a.w);
    p.h[2] = __floats2half2_rn(b.x, b.y);
    p.h[3] = __floats2half2_rn(b.z, b.w);
    dst[j] = p.u;
}

// ---------------- RoPE table ------------------------------------------------
__global__ void rope_table_kernel(const int* __restrict__ pos)
{
    int t = blockIdx.x;
    int i = threadIdx.x;          // 0..31
    double inv = pow(10000.0, -((double)(2*i) / 64.0));
    float ang = (float)pos[t] * (float)inv;
    g_cos[t*32 + i] = cosf(ang);
    g_sin[t*32 + i] = sinf(ang);
}

// ---------------- FP16 mma GEMM core (4-stage cp.async ring) -----------------
#define GROWB 80                    // bytes per smem row
#define GTILEB (128*GROWB)          // 10240 B per tile buffer
#define GEMM_SMEM_BYTES (8*GTILEB)  // 4 stages x (A,B) = 81920 B (dynamic)
#define NKCH (D_MODEL/32)           // 32 k-chunks

struct GemmAcc { float4 acc[4][4]; };

__device__ __forceinline__ void gemm_core(
    const __half* __restrict__ Xrow,
    const __half* __restrict__ Wrow,
    char* dsm, GemmAcc& R, int tid, int wm, int wn, int lane)
{
    #pragma unroll
    for (int i = 0; i < 4; i++)
        #pragma unroll
        for (int j = 0; j < 4; j++) R.acc[i][j] = make_float4(0.f,0.f,0.f,0.f);

    const int row  = tid >> 1;
    const int hofB = (tid & 1) * 32;

    const int arow = lane & 15;
    const int acB  = (lane >> 4) * 16;
    const int brow = ((lane >> 4) << 3) + (lane & 7);
    const int bcB  = ((lane >> 3) & 1) * 16;

    auto stage = [&](int chunk, int buf) {
        char* A = dsm + buf * (2*GTILEB);
        char* B = A + GTILEB;
        #pragma unroll
        for (int c = 0; c < 2; c++) {
            cpa16(s2u(A + row*GROWB + hofB + c*16), Xrow + chunk*32 + c*8);
            cpa16(s2u(B + row*GROWB + hofB + c*16), Wrow + chunk*32 + c*8);
        }
    };

    stage(0, 0); CP_COMMIT();
    stage(1, 1); CP_COMMIT();

    for (int i = 0; i < NKCH; i++) {
        CP_WAIT1();
        __syncthreads();               // chunk i staged & visible to all
        const int cb = i & 3;
        if (i + 2 < NKCH) stage(i + 2, (i + 2) & 3);
        CP_COMMIT();                   // may be empty near the end

        char* Ac = dsm + cb * (2*GTILEB);
        char* Bc = Ac + GTILEB;
        uint32_t abase = s2u(Ac + (wm*64 + arow)*GROWB + acB);
        uint32_t bbase = s2u(Bc + (wn*32 + brow)*GROWB + bcB);
        #pragma unroll
        for (int ks = 0; ks < 2; ks++) {
            uint32_t af[4][4];
            #pragma unroll
            for (int mt = 0; mt < 4; mt++)
                ldsm4(af[mt][0], af[mt][1], af[mt][2], af[mt][3],
                      abase + (uint32_t)(mt*16*GROWB + ks*32));
            #pragma unroll
            for (int ntp = 0; ntp < 2; ntp++) {
                uint32_t b0, b1, b2, b3;
                ldsm4(b0, b1, b2, b3, bbase + (uint32_t)(ntp*16*GROWB + ks*32));
                #pragma unroll
                for (int mt = 0; mt < 4; mt++) {
                    mma16(R.acc[mt][2*ntp  ], af[mt][0],af[mt][1],af[mt][2],af[mt][3], b0, b1);
                    mma16(R.acc[mt][2*ntp+1], af[mt][0],af[mt][1],af[mt][2],af[mt][3], b2, b3);
                }
            }
        }
    }
}

// ---------------- Q/K projection + RoPE epilogue ----------------------------
__global__ __launch_bounds__(256) void qk_gemm_kernel(
    const float* __restrict__ bq, const float* __restrict__ bk)
{
    extern __shared__ char dsm[];
    const __half* W    = blockIdx.z ? g_Wkh : g_Wqh;
    const float*  bias = blockIdx.z ? bk : bq;

    const int tid = threadIdx.x, lane = tid & 31, warp = tid >> 5;
    const int wm = warp >> 2, wn = warp & 3;
    const int g = lane >> 2, t = lane & 3;
    const int m0 = blockIdx.y * 128, n0 = blockIdx.x * 128;
    const int row = tid >> 1, hoff = (tid & 1) * 16;

    GemmAcc R;
    gemm_core(g_Xh + (size_t)(m0 + row) * D_MODEL + hoff,
              W    + (size_t)(n0 + row) * D_MODEL + hoff,
              dsm, R, tid, wm, wn, lane);

    __half* outR = blockIdx.z ? g_Kr : g_Qr;
    const bool writeV = (blockIdx.z == 0);
    const float sc = writeV ? EXP_SCALE : 1.0f;   // fold softmax scale into Q

    #pragma unroll
    for (int mt = 0; mt < 4; mt++) {
        int r1 = m0 + wm*64 + mt*16 + g;
        int r2 = r1 + 8;
        int t1 = r1 & (TT-1), t2 = r2 & (TT-1);
        int b1i = r1 >> 11, b2i = r2 >> 11;
        #pragma unroll
        for (int nt = 0; nt < 4; nt++) {
            int n = n0 + wn*32 + nt*8 + 2*t;
            float b0v = bias[n], b1v = bias[n+1];
            int fi = (n & 63) >> 1;
            float4 c = R.acc[mt][nt];
            float y1 = c.x + b0v, y2 = c.y + b1v;
            float z1 = c.z + b0v, z2 = c.w + b1v;
            if (writeV) {
                int h = n >> 6, d = n & 63;
                size_t vb1 = ((size_t)(b1i*NHEADS + h)*DK + d)*TT;
                size_t vb2 = ((size_t)(b2i*NHEADS + h)*DK + d)*TT;
                g_Vt[vb1 + t1]      = __float2half_rn(y1);
                g_Vt[vb1 + TT + t1] = __float2half_rn(y2);
                g_Vt[vb2 + t2]      = __float2half_rn(z1);
                g_Vt[vb2 + TT + t2] = __float2half_rn(z2);
            }
            float c1 = g_cos[t1*32+fi], s1 = g_sin[t1*32+fi];
            float c2 = g_cos[t2*32+fi], s2 = g_sin[t2*32+fi];
            *(__half2*)&outR[(size_t)r1*D_MODEL + n] =
                __floats2half2_rn((y1*c1 - y2*s1)*sc, (y1*s1 + y2*c1)*sc);
            *(__half2*)&outR[(size_t)r2*D_MODEL + n] =
                __floats2half2_rn((z1*c2 - z2*s2)*sc, (z1*s2 + z2*c2)*sc);
        }
    }
}

// ---------------- output projection -----------------------------------------
__global__ __launch_bounds__(256) void o_gemm_kernel(
    const float* __restrict__ bias, float* __restrict__ Y)
{
    extern __shared__ char dsm[];
    const int tid = threadIdx.x, lane = tid & 31, warp = tid >> 5;
    const int wm = warp >> 2, wn = warp & 3;
    const int g = lane >> 2, t = lane & 3;
    const int m0 = blockIdx.y * 128, n0 = blockIdx.x * 128;
    const int row = tid >> 1, hoff = (tid & 1) * 16;

    GemmAcc R;
    gemm_core(g_Attn + (size_t)(m0 + row) * D_MODEL + hoff,
              g_Woh  + (size_t)(n0 + row) * D_MODEL + hoff,
              dsm, R, tid, wm, wn, lane);

    #pragma unroll
    for (int mt = 0; mt < 4; mt++) {
        int r1 = m0 + wm*64 + mt*16 + g;
        int r2 = r1 + 8;
        #pragma unroll
        for (int nt = 0; nt < 4; nt++) {
            int n = n0 + wn*32 + nt*8 + 2*t;
            float b0v = bias[n], b1v = bias[n+1];
            float4 c = R.acc[mt][nt];
            *(float2*)&Y[(size_t)r1*D_MODEL + n] = make_float2(c.x + b0v, c.y + b1v);
            *(float2*)&Y[(size_t)r2*D_MODEL + n] = make_float2(c.z + b0v, c.w + b1v);
        }
    }
}

// ---------------- flash attention (4-buffer ring, f16x2 exp, reg P) ---------
// One __syncthreads per tile: with a 4-deep K/V ring, PV reads V[jt-1], S
// reads K[jt], prefetch writes buf[(jt+2)&3] -- all distinct mod 4, and the
// top-of-loop barrier (all warps finished iter jt-1) protects buf[(jt+2)&3]
// from lagging readers. exp via ex2.approx.f16x2 (masked lanes -> -inf -> 0).
#define AROWB 144
#define KTILEB (64*AROWB)                       // 9216 B
#define ATT_SMEM_BYTES (8*KTILEB)               // 4 x (K,V) = 73728 B
#define ONE2 0x3C003C00u                        // half2(1.0, 1.0)

__global__ __launch_bounds__(256) void attn_kernel()
{
    extern __shared__ char asm_[];
    char* KsB[4] = { asm_,            asm_ + 2*KTILEB,
                     asm_ + 4*KTILEB, asm_ + 6*KTILEB };
    char* VsB[4] = { asm_ + KTILEB,   asm_ + 3*KTILEB,
                     asm_ + 5*KTILEB, asm_ + 7*KTILEB };

    const int tid = threadIdx.x, lane = tid & 31, warp = tid >> 5;
    const int g = lane >> 2, t = lane & 3;
    const int h = blockIdx.y, b = blockIdx.z;
    const int qbase = (gridDim.x - 1 - blockIdx.x) * 128;  // big tiles first
    const size_t base = (size_t)b * TT * D_MODEL + h * DK;
    const __half* Qb  = g_Qr + base;
    const __half* Kb  = g_Kr + base;
    const __half* Vtb = g_Vt + (size_t)(b*NHEADS + h) * DK * TT;

    const int srj  = tid >> 2;
    const int hoff = (tid & 3) * 16;
    const __half* ksrc = Kb  + (size_t)srj * D_MODEL + hoff;
    const __half* vsrc = Vtb + (size_t)srj * TT + hoff;

    const int brow = ((lane >> 4) << 3) + (lane & 7);
    const int bcB  = ((lane >> 3) & 1) * 16;

    // Q fragments in registers
    uint32_t qa[4][4];
    {
        const __half* q1 = Qb + (size_t)(qbase + warp*16 + g) * D_MODEL;
        const __half* q2 = q1 + (size_t)8 * D_MODEL;
        #pragma unroll
        for (int kc = 0; kc < 4; kc++) {
            qa[kc][0] = *(const uint32_t*)(q1 + kc*16 + 2*t);
            qa[kc][1] = *(const uint32_t*)(q2 + kc*16 + 2*t);
            qa[kc][2] = *(const uint32_t*)(q1 + kc*16 + 2*t + 8);
            qa[kc][3] = *(const uint32_t*)(q2 + kc*16 + 2*t + 8);
        }
    }

    float4 oacc[8];
    #pragma unroll
    for (int nt = 0; nt < 8; nt++) oacc[nt] = make_float4(0.f,0.f,0.f,0.f);
    float4 osum = make_float4(0.f,0.f,0.f,0.f);   // row sums via ones mma
    uint32_t pa[4][4];                            // P(jt-1) fragments (fp16)

    const int qi1 = qbase + warp*16 + g;
    const int qi2 = qi1 + 8;
    const int wrow0 = qbase + warp*16;            // warp's min q row
    const int nkv = (qbase + 128) / 64;           // >= 2 always
    bool pdead = true;                            // P(jt-1) absent

    auto stageKV = [&](int jtile, int buf) {
        const size_t koff = (size_t)(jtile*64) * D_MODEL;
        const int    voff = jtile*64;
        #pragma unroll
        for (int c = 0; c < 2; c++) {
            cpa16(s2u(KsB[buf] + srj*AROWB + hoff*2 + c*16), ksrc + koff + c*8);
            cpa16(s2u(VsB[buf] + srj*AROWB + hoff*2 + c*16), vsrc + voff + c*8);
        }
    };

    stageKV(0, 0); CP_COMMIT();
    stageKV(1, 1); CP_COMMIT();

    for (int jt = 0; jt < nkv; jt++) {
        const int j0 = jt * 64;
        CP_WAIT1();
        __syncthreads();          // K/V(jt) staged & visible; iter jt-1 done
        const int cb = jt & 3;
        const int pb = (jt + 3) & 3;

        // ---- PV(jt-1): register P against V[pb] ----
        if (!pdead) {
            const uint32_t vbase = s2u(VsB[pb] + brow*AROWB + bcB);
            #pragma unroll
            for (int kc = 0; kc < 4; kc++) {
                #pragma unroll
                for (int ntp = 0; ntp < 4; ntp++) {
                    uint32_t b0, b1, b2, b3;
                    ldsm4(b0, b1, b2, b3, vbase + (uint32_t)(ntp*16*AROWB + kc*32));
                    mma16(oacc[2*ntp  ], pa[kc][0], pa[kc][1], pa[kc][2], pa[kc][3], b0, b1);
                    mma16(oacc[2*ntp+1], pa[kc][0], pa[kc][1], pa[kc][2], pa[kc][3], b2, b3);
                }
                mma16(osum, pa[kc][0], pa[kc][1], pa[kc][2], pa[kc][3], ONE2, ONE2);
            }
        }

        // ---- prefetch K/V(jt+2) into (jt+2)&3 ----
        if (jt + 2 < nkv) stageKV(jt + 2, (jt + 2) & 3);
        CP_COMMIT();              // may be empty near the end

        // ---- S(jt) + f16x2 exp -> register P; skip fully-masked tiles -----
        const bool dead = (j0 > wrow0 + 15);   // warp-uniform
        if (!dead) {
            const bool full = (j0 + 63 <= wrow0);
            const uint32_t kbase = s2u(KsB[cb] + brow*AROWB + bcB);
            #pragma unroll
            for (int ntp = 0; ntp < 4; ntp++) {
                float4 s0 = make_float4(0.f,0.f,0.f,0.f);
                float4 s1 = make_float4(0.f,0.f,0.f,0.f);
                #pragma unroll
                for (int kc = 0; kc < 4; kc++) {
                    uint32_t b0, b1, b2, b3;
                    ldsm4(b0, b1, b2, b3, kbase + (uint32_t)(ntp*16*AROWB + kc*32));
                    mma16(s0, qa[kc][0], qa[kc][1], qa[kc][2], qa[kc][3], b0, b1);
                    mma16(s1, qa[kc][0], qa[kc][1], qa[kc][2], qa[kc][3], b2, b3);
                }
                if (!full) {
                    int c0 = j0 + ntp*16 + 2*t;
                    int c1 = c0 + 8;
                    s0.x = (c0   <= qi1) ? s0.x : -1e30f;
                    s0.y = (c0+1 <= qi1) ? s0.y : -1e30f;
                    s0.z = (c0   <= qi2) ? s0.z : -1e30f;
                    s0.w = (c0+1 <= qi2) ? s0.w : -1e30f;
                    s1.x = (c1   <= qi1) ? s1.x : -1e30f;
                    s1.y = (c1+1 <= qi1) ? s1.y : -1e30f;
                    s1.z = (c1   <= qi2) ? s1.z : -1e30f;
                    s1.w = (c1+1 <= qi2) ? s1.w : -1e30f;
                }
                pa[ntp][0] = h2ex2(pack_h2(s0.x, s0.y));
                pa[ntp][1] = h2ex2(pack_h2(s0.z, s0.w));
                pa[ntp][2] = h2ex2(pack_h2(s1.x, s1.y));
                pa[ntp][3] = h2ex2(pack_h2(s1.z, s1.w));
            }
        }
        pdead = dead;
    }

    // ---- epilogue: final PV + normalize ----
    if (!pdead) {
        const int pb = (nkv - 1) & 3;
        const uint32_t vbase = s2u(VsB[pb] + brow*AROWB + bcB);
        #pragma unroll
        for (int kc = 0; kc < 4; kc++) {
            #pragma unroll
            for (int ntp = 0; ntp < 4; ntp++) {
                uint32_t b0, b1, b2, b3;
                ldsm4(b0, b1, b2, b3, vbase + (uint32_t)(ntp*16*AROWB + kc*32));
                mma16(oacc[2*ntp  ], pa[kc][0], pa[kc][1], pa[kc][2], pa[kc][3], b0, b1);
                mma16(oacc[2*ntp+1], pa[kc][0], pa[kc][1], pa[kc][2], pa[kc][3], b2, b3);
            }
            mma16(osum, pa[kc][0], pa[kc][1], pa[kc][2], pa[kc][3], ONE2, ONE2);
        }
    }

    float il0 = 1.f / osum.x, il1 = 1.f / osum.z;
    const size_t r1off = base + (size_t)qi1 * D_MODEL;
    const size_t r2off = base + (size_t)qi2 * D_MODEL;
    #pragma unroll
    for (int nt = 0; nt < 8; nt++) {
        int col = nt*8 + 2*t;
        *(__half2*)&g_Attn[r1off + col] =
            __floats2half2_rn(oacc[nt].x*il0, oacc[nt].y*il0);
        *(__half2*)&g_Attn[r2off + col] =
            __floats2half2_rn(oacc[nt].z*il1, oacc[nt].w*il1);
    }
}

// ---------------- launch ----------------------------------------------------
extern "C" void kernel_launch(void* const* d_in, const int* in_sizes, int n_in,
                              void* d_out, int out_size)
{
    (void)in_sizes; (void)n_in; (void)out_size;
    const float* x   = (const float*)d_in[0];
    const int*   pos = (const int*)  d_in[1];
    const float* Wq  = (const float*)d_in[2];
    const float* bq  = (const float*)d_in[3];
    const float* Wk  = (const float*)d_in[4];
    const float* bk  = (const float*)d_in[5];
    // d_in[6], d_in[7] (Wv, bv) unused: reference computes V with Wq/bq
    const float* Wo  = (const float*)d_in[8];
    const float* bo  = (const float*)d_in[9];
    float* out = (float*)d_out;

    cudaFuncSetAttribute(attn_kernel,
                         cudaFuncAttributeMaxDynamicSharedMemorySize, ATT_SMEM_BYTES);
    cudaFuncSetAttribute(qk_gemm_kernel,
                         cudaFuncAttributeMaxDynamicSharedMemorySize, GEMM_SMEM_BYTES);
    cudaFuncSetAttribute(o_gemm_kernel,
                         cudaFuncAttributeMaxDynamicSharedMemorySize, GEMM_SMEM_BYTES);

    rope_table_kernel<<<TT, 32>>>(pos);

    f2h_all_kernel<<<(NALL8 + 255)/256, 256>>>(
        (const float4*)x, (const float4*)Wq,
        (const float4*)Wk, (const float4*)Wo);

    dim3 gq(D_MODEL/128, MTOT/128, 2);
    qk_gemm_kernel<<<gq, 256, GEMM_SMEM_BYTES>>>(bq, bk);

    dim3 ga(TT/128, NHEADS, BB);
    attn_kernel<<<ga, 256, ATT_SMEM_BYTES>>>();

    dim3 go(D_MODEL/128, MTOT/128, 1);
    o_gemm_kernel<<<go, 256, GEMM_SMEM_BYTES>>>(bo, out);
}

// round 14
// speedup vs baseline: 1.0431x; 1.0431x over previous
#include <cuda_runtime.h>
#include <cuda_fp16.h>
#include <math.h>
#include <stdint.h>

#define D_MODEL 1024
#define NHEADS  16
#define DK      64
#define BB      2
#define TT      2048
#define MTOT    (BB*TT)   // 4096 rows

// ---------------- scratch (static device arrays; no allocation allowed) ----
__device__ __half g_Qr[MTOT*D_MODEL];    // RoPE'd Q, pre-scaled by 0.125*log2(e)
__device__ __half g_Kr[MTOT*D_MODEL];    // RoPE'd K (fp16)
__device__ __half g_Vt[MTOT*D_MODEL];    // V transposed [b,h,d,t] (fp16)
__device__ __half g_Attn[MTOT*D_MODEL];  // attention output (fp16)
__device__ __half g_Xh[MTOT*D_MODEL];    // input x (fp16)
__device__ __half g_Wqh[D_MODEL*D_MODEL];
__device__ __half g_Wkh[D_MODEL*D_MODEL];
__device__ __half g_Woh[D_MODEL*D_MODEL];
__device__ float  g_cos[TT*32];
__device__ float  g_sin[TT*32];

#define EXP_SCALE 0.180336880111120405f   // 0.125 * log2(e), folded into Q

// ---------------- helpers ---------------------------------------------------
__device__ __forceinline__ void mma16(float4& c,
    uint32_t a0, uint32_t a1, uint32_t a2, uint32_t a3,
    uint32_t b0, uint32_t b1)
{
    asm volatile(
        "mma.sync.aligned.m16n8k16.row.col.f32.f16.f16.f32 "
        "{%0,%1,%2,%3}, {%4,%5,%6,%7}, {%8,%9}, {%0,%1,%2,%3};\n"
        : "+f"(c.x), "+f"(c.y), "+f"(c.z), "+f"(c.w)
        : "r"(a0), "r"(a1), "r"(a2), "r"(a3), "r"(b0), "r"(b1));
}

__device__ __forceinline__ void ldsm4(uint32_t& r0, uint32_t& r1,
                                      uint32_t& r2, uint32_t& r3, uint32_t addr)
{
    asm volatile("ldmatrix.sync.aligned.m8n8.x4.shared.b16 {%0,%1,%2,%3}, [%4];"
                 : "=r"(r0), "=r"(r1), "=r"(r2), "=r"(r3) : "r"(addr));
}

__device__ __forceinline__ uint32_t s2u(const void* p)
{
    return (uint32_t)__cvta_generic_to_shared(p);
}

__device__ __forceinline__ void cpa16(uint32_t dst, const void* src)
{
    asm volatile("cp.async.cg.shared.global [%0], [%1], 16;" :: "r"(dst), "l"(src));
}
#define CP_COMMIT() asm volatile("cp.async.commit_group;" ::: "memory")
#define CP_WAIT0()  asm volatile("cp.async.wait_group 0;" ::: "memory")
#define CP_WAIT1()  asm volatile("cp.async.wait_group 1;" ::: "memory")

__device__ __forceinline__ uint32_t pack_h2(float x, float y)
{
    __half2 h = __floats2half2_rn(x, y);
    return *(uint32_t*)&h;
}

__device__ __forceinline__ uint32_t h2ex2(uint32_t u)
{
    uint32_t r;
    asm("ex2.approx.f16x2 %0, %1;" : "=r"(r) : "r"(u));
    return r;
}

// ---------------- prepass: fused f32 -> f16 for x, Wq, Wk, Wo ----------------
#define NX8 (MTOT*D_MODEL/8)       // 524288
#define NW8 (D_MODEL*D_MODEL/8)    // 131072
#define NALL8 (NX8 + 3*NW8)        // 917504

__global__ void f2h_all_kernel(const float4* __restrict__ x,
                               const float4* __restrict__ wq,
                               const float4* __restrict__ wk,
                               const float4* __restrict__ wo)
{
    int i = blockIdx.x * blockDim.x + threadIdx.x;
    if (i >= NALL8) return;
    const float4* src;
    uint4* dst;
    int j;
    if (i < NX8)               { src = x;  dst = (uint4*)g_Xh;  j = i; }
    else if (i < NX8 + NW8)    { src = wq; dst = (uint4*)g_Wqh; j = i - NX8; }
    else if (i < NX8 + 2*NW8)  { src = wk; dst = (uint4*)g_Wkh; j = i - NX8 - NW8; }
    else                       { src = wo; dst = (uint4*)g_Woh; j = i - NX8 - 2*NW8; }
    float4 a = src[2*j], b = src[2*j+1];
    union { uint4 u; __half2 h[4]; } p;
    p.h[0] = __floats2half2_rn(a.x, a.y);
    p.h[1] = __floats2half2_rn(a.z, a.w);
    p.h[2] = __floats2half2_rn(b.x, b.y);
    p.h[3] = __floats2half2_rn(b.z, b.w);
    dst[j] = p.u;
}

// ---------------- RoPE table ------------------------------------------------
__global__ void rope_table_kernel(const int* __restrict__ pos)
{
    int t = blockIdx.x;
    int i = threadIdx.x;          // 0..31
    double inv = pow(10000.0, -((double)(2*i) / 64.0));
    float ang = (float)pos[t] * (float)inv;
    g_cos[t*32 + i] = cosf(ang);
    g_sin[t*32 + i] = sinf(ang);
}

// ---------------- FP16 mma GEMM core (2-stage, static smem) ------------------
#define GROWB 80                    // bytes per smem row
#define GTILEB (128*GROWB)          // 10240 B per tile buffer
#define GEMM_SMEM_BYTES (4*GTILEB)  // A0,B0,A1,B1 = 40960 B (static)

struct GemmAcc { float4 acc[4][4]; };

__device__ __forceinline__ void gemm_core(
    const __half* __restrict__ Xrow,
    const __half* __restrict__ Wrow,
    char* gsm, GemmAcc& R, int tid, int wm, int wn, int lane)
{
    char* A0 = gsm;
    char* B0 = gsm + GTILEB;
    char* A1 = gsm + 2*GTILEB;
    char* B1 = gsm + 3*GTILEB;

    #pragma unroll
    for (int i = 0; i < 4; i++)
        #pragma unroll
        for (int j = 0; j < 4; j++) R.acc[i][j] = make_float4(0.f,0.f,0.f,0.f);

    const int row  = tid >> 1;
    const int hofB = (tid & 1) * 32;

    const int arow = lane & 15;
    const int acB  = (lane >> 4) * 16;
    const int brow = ((lane >> 4) << 3) + (lane & 7);
    const int bcB  = ((lane >> 3) & 1) * 16;

    #pragma unroll
    for (int c = 0; c < 2; c++) {
        cpa16(s2u(A0 + row*GROWB + hofB + c*16), Xrow + c*8);
        cpa16(s2u(B0 + row*GROWB + hofB + c*16), Wrow + c*8);
    }
    CP_COMMIT();

    for (int k0 = 0; k0 < D_MODEL; k0 += 32) {
        CP_WAIT0();
        __syncthreads();
        char* Ac = (k0 & 32) ? A1 : A0;
        char* Bc = (k0 & 32) ? B1 : B0;
        if (k0 + 32 < D_MODEL) {
            char* An = (k0 & 32) ? A0 : A1;
            char* Bn = (k0 & 32) ? B0 : B1;
            #pragma unroll
            for (int c = 0; c < 2; c++) {
                cpa16(s2u(An + row*GROWB + hofB + c*16), Xrow + k0 + 32 + c*8);
                cpa16(s2u(Bn + row*GROWB + hofB + c*16), Wrow + k0 + 32 + c*8);
            }
            CP_COMMIT();
        }
        uint32_t abase = s2u(Ac + (wm*64 + arow)*GROWB + acB);
        uint32_t bbase = s2u(Bc + (wn*32 + brow)*GROWB + bcB);
        #pragma unroll
        for (int ks = 0; ks < 2; ks++) {
            uint32_t af[4][4];
            #pragma unroll
            for (int mt = 0; mt < 4; mt++)
                ldsm4(af[mt][0], af[mt][1], af[mt][2], af[mt][3],
                      abase + (uint32_t)(mt*16*GROWB + ks*32));
            #pragma unroll
            for (int ntp = 0; ntp < 2; ntp++) {
                uint32_t b0, b1, b2, b3;
                ldsm4(b0, b1, b2, b3, bbase + (uint32_t)(ntp*16*GROWB + ks*32));
                #pragma unroll
                for (int mt = 0; mt < 4; mt++) {
                    mma16(R.acc[mt][2*ntp  ], af[mt][0],af[mt][1],af[mt][2],af[mt][3], b0, b1);
                    mma16(R.acc[mt][2*ntp+1], af[mt][0],af[mt][1],af[mt][2],af[mt][3], b2, b3);
                }
            }
        }
    }
}

// ---------------- Q/K projection + RoPE epilogue ----------------------------
__global__ __launch_bounds__(256) void qk_gemm_kernel(
    const float* __restrict__ bq, const float* __restrict__ bk)
{
    __shared__ __align__(16) char gsm[GEMM_SMEM_BYTES];
    const __half* W    = blockIdx.z ? g_Wkh : g_Wqh;
    const float*  bias = blockIdx.z ? bk : bq;

    const int tid = threadIdx.x, lane = tid & 31, warp = tid >> 5;
    const int wm = warp >> 2, wn = warp & 3;
    const int g = lane >> 2, t = lane & 3;
    const int m0 = blockIdx.y * 128, n0 = blockIdx.x * 128;
    const int row = tid >> 1, hoff = (tid & 1) * 16;

    GemmAcc R;
    gemm_core(g_Xh + (size_t)(m0 + row) * D_MODEL + hoff,
              W    + (size_t)(n0 + row) * D_MODEL + hoff,
              gsm, R, tid, wm, wn, lane);

    __half* outR = blockIdx.z ? g_Kr : g_Qr;
    const bool writeV = (blockIdx.z == 0);
    const float sc = writeV ? EXP_SCALE : 1.0f;   // fold softmax scale into Q

    #pragma unroll
    for (int mt = 0; mt < 4; mt++) {
        int r1 = m0 + wm*64 + mt*16 + g;
        int r2 = r1 + 8;
        int t1 = r1 & (TT-1), t2 = r2 & (TT-1);
        int b1i = r1 >> 11, b2i = r2 >> 11;
        #pragma unroll
        for (int nt = 0; nt < 4; nt++) {
            int n = n0 + wn*32 + nt*8 + 2*t;
            float b0v = bias[n], b1v = bias[n+1];
            int fi = (n & 63) >> 1;
            float4 c = R.acc[mt][nt];
            float y1 = c.x + b0v, y2 = c.y + b1v;
            float z1 = c.z + b0v, z2 = c.w + b1v;
            if (writeV) {
                int h = n >> 6, d = n & 63;
                size_t vb1 = ((size_t)(b1i*NHEADS + h)*DK + d)*TT;
                size_t vb2 = ((size_t)(b2i*NHEADS + h)*DK + d)*TT;
                g_Vt[vb1 + t1]      = __float2half_rn(y1);
                g_Vt[vb1 + TT + t1] = __float2half_rn(y2);
                g_Vt[vb2 + t2]      = __float2half_rn(z1);
                g_Vt[vb2 + TT + t2] = __float2half_rn(z2);
            }
            float c1 = g_cos[t1*32+fi], s1 = g_sin[t1*32+fi];
            float c2 = g_cos[t2*32+fi], s2 = g_sin[t2*32+fi];
            *(__half2*)&outR[(size_t)r1*D_MODEL + n] =
                __floats2half2_rn((y1*c1 - y2*s1)*sc, (y1*s1 + y2*c1)*sc);
            *(__half2*)&outR[(size_t)r2*D_MODEL + n] =
                __floats2half2_rn((z1*c2 - z2*s2)*sc, (z1*s2 + z2*c2)*sc);
        }
    }
}

// ---------------- output projection -----------------------------------------
__global__ __launch_bounds__(256) void o_gemm_kernel(
    const float* __restrict__ bias, float* __restrict__ Y)
{
    __shared__ __align__(16) char gsm[GEMM_SMEM_BYTES];
    const int tid = threadIdx.x, lane = tid & 31, warp = tid >> 5;
    const int wm = warp >> 2, wn = warp & 3;
    const int g = lane >> 2, t = lane & 3;
    const int m0 = blockIdx.y * 128, n0 = blockIdx.x * 128;
    const int row = tid >> 1, hoff = (tid & 1) * 16;

    GemmAcc R;
    gemm_core(g_Attn + (size_t)(m0 + row) * D_MODEL + hoff,
              g_Woh  + (size_t)(n0 + row) * D_MODEL + hoff,
              gsm, R, tid, wm, wn, lane);

    #pragma unroll
    for (int mt = 0; mt < 4; mt++) {
        int r1 = m0 + wm*64 + mt*16 + g;
        int r2 = r1 + 8;
        #pragma unroll
        for (int nt = 0; nt < 4; nt++) {
            int n = n0 + wn*32 + nt*8 + 2*t;
            float b0v = bias[n], b1v = bias[n+1];
            float4 c = R.acc[mt][nt];
            *(float2*)&Y[(size_t)r1*D_MODEL + n] = make_float2(c.x + b0v, c.y + b1v);
            *(float2*)&Y[(size_t)r2*D_MODEL + n] = make_float2(c.z + b0v, c.w + b1v);
        }
    }
}

// ---------------- flash attention (4-buffer ring, f16x2 exp, reg P) ---------
// One __syncthreads per tile: with a 4-deep K/V ring, PV reads V[jt-1], S
// reads K[jt], prefetch writes buf[(jt+2)&3] -- all distinct mod 4, and the
// top-of-loop barrier (all warps finished iter jt-1) protects buf[(jt+2)&3]
// from lagging readers. exp via ex2.approx.f16x2 (masked lanes -> -inf -> 0).
#define AROWB 144
#define KTILEB (64*AROWB)                       // 9216 B
#define ATT_SMEM_BYTES (8*KTILEB)               // 4 x (K,V) = 73728 B
#define ONE2 0x3C003C00u                        // half2(1.0, 1.0)

__global__ __launch_bounds__(256) void attn_kernel()
{
    extern __shared__ char asm_[];
    char* KsB[4] = { asm_,            asm_ + 2*KTILEB,
                     asm_ + 4*KTILEB, asm_ + 6*KTILEB };
    char* VsB[4] = { asm_ + KTILEB,   asm_ + 3*KTILEB,
                     asm_ + 5*KTILEB, asm_ + 7*KTILEB };

    const int tid = threadIdx.x, lane = tid & 31, warp = tid >> 5;
    const int g = lane >> 2, t = lane & 3;
    const int h = blockIdx.y, b = blockIdx.z;
    const int qbase = (gridDim.x - 1 - blockIdx.x) * 128;  // big tiles first
    const size_t base = (size_t)b * TT * D_MODEL + h * DK;
    const __half* Qb  = g_Qr + base;
    const __half* Kb  = g_Kr + base;
    const __half* Vtb = g_Vt + (size_t)(b*NHEADS + h) * DK * TT;

    const int srj  = tid >> 2;
    const int hoff = (tid & 3) * 16;
    const __half* ksrc = Kb  + (size_t)srj * D_MODEL + hoff;
    const __half* vsrc = Vtb + (size_t)srj * TT + hoff;

    const int brow = ((lane >> 4) << 3) + (lane & 7);
    const int bcB  = ((lane >> 3) & 1) * 16;

    // Q fragments in registers
    uint32_t qa[4][4];
    {
        const __half* q1 = Qb + (size_t)(qbase + warp*16 + g) * D_MODEL;
        const __half* q2 = q1 + (size_t)8 * D_MODEL;
        #pragma unroll
        for (int kc = 0; kc < 4; kc++) {
            qa[kc][0] = *(const uint32_t*)(q1 + kc*16 + 2*t);
            qa[kc][1] = *(const uint32_t*)(q2 + kc*16 + 2*t);
            qa[kc][2] = *(const uint32_t*)(q1 + kc*16 + 2*t + 8);
            qa[kc][3] = *(const uint32_t*)(q2 + kc*16 + 2*t + 8);
        }
    }

    float4 oacc[8];
    #pragma unroll
    for (int nt = 0; nt < 8; nt++) oacc[nt] = make_float4(0.f,0.f,0.f,0.f);
    float4 osum = make_float4(0.f,0.f,0.f,0.f);   // row sums via ones mma
    uint32_t pa[4][4];                            // P(jt-1) fragments (fp16)

    const int qi1 = qbase + warp*16 + g;
    const int qi2 = qi1 + 8;
    const int wrow0 = qbase + warp*16;            // warp's min q row
    const int nkv = (qbase + 128) / 64;           // >= 2 always
    bool pdead = true;                            // P(jt-1) absent

    auto stageKV = [&](int jtile, int buf) {
        const size_t koff = (size_t)(jtile*64) * D_MODEL;
        const int    voff = jtile*64;
        #pragma unroll
        for (int c = 0; c < 2; c++) {
            cpa16(s2u(KsB[buf] + srj*AROWB + hoff*2 + c*16), ksrc + koff + c*8);
            cpa16(s2u(VsB[buf] + srj*AROWB + hoff*2 + c*16), vsrc + voff + c*8);
        }
    };

    stageKV(0, 0); CP_COMMIT();
    stageKV(1, 1); CP_COMMIT();

    for (int jt = 0; jt < nkv; jt++) {
        const int j0 = jt * 64;
        CP_WAIT1();
        __syncthreads();          // K/V(jt) staged & visible; iter jt-1 done
        const int cb = jt & 3;
        const int pb = (jt + 3) & 3;

        // ---- PV(jt-1): register P against V[pb] ----
        if (!pdead) {
            const uint32_t vbase = s2u(VsB[pb] + brow*AROWB + bcB);
            #pragma unroll
            for (int kc = 0; kc < 4; kc++) {
                #pragma unroll
                for (int ntp = 0; ntp < 4; ntp++) {
                    uint32_t b0, b1, b2, b3;
                    ldsm4(b0, b1, b2, b3, vbase + (uint32_t)(ntp*16*AROWB + kc*32));
                    mma16(oacc[2*ntp  ], pa[kc][0], pa[kc][1], pa[kc][2], pa[kc][3], b0, b1);
                    mma16(oacc[2*ntp+1], pa[kc][0], pa[kc][1], pa[kc][2], pa[kc][3], b2, b3);
                }
                mma16(osum, pa[kc][0], pa[kc][1], pa[kc][2], pa[kc][3], ONE2, ONE2);
            }
        }

        // ---- prefetch K/V(jt+2) into (jt+2)&3 ----
        if (jt + 2 < nkv) stageKV(jt + 2, (jt + 2) & 3);
        CP_COMMIT();              // may be empty near the end

        // ---- S(jt) + f16x2 exp -> register P; skip fully-masked tiles -----
        const bool dead = (j0 > wrow0 + 15);   // warp-uniform
        if (!dead) {
            const bool full = (j0 + 63 <= wrow0);
            const uint32_t kbase = s2u(KsB[cb] + brow*AROWB + bcB);
            #pragma unroll
            for (int ntp = 0; ntp < 4; ntp++) {
                float4 s0 = make_float4(0.f,0.f,0.f,0.f);
                float4 s1 = make_float4(0.f,0.f,0.f,0.f);
                #pragma unroll
                for (int kc = 0; kc < 4; kc++) {
                    uint32_t b0, b1, b2, b3;
                    ldsm4(b0, b1, b2, b3, kbase + (uint32_t)(ntp*16*AROWB + kc*32));
                    mma16(s0, qa[kc][0], qa[kc][1], qa[kc][2], qa[kc][3], b0, b1);
                    mma16(s1, qa[kc][0], qa[kc][1], qa[kc][2], qa[kc][3], b2, b3);
                }
                if (!full) {
                    int c0 = j0 + ntp*16 + 2*t;
                    int c1 = c0 + 8;
                    s0.x = (c0   <= qi1) ? s0.x : -1e30f;
                    s0.y = (c0+1 <= qi1) ? s0.y : -1e30f;
                    s0.z = (c0   <= qi2) ? s0.z : -1e30f;
                    s0.w = (c0+1 <= qi2) ? s0.w : -1e30f;
                    s1.x = (c1   <= qi1) ? s1.x : -1e30f;
                    s1.y = (c1+1 <= qi1) ? s1.y : -1e30f;
                    s1.z = (c1   <= qi2) ? s1.z : -1e30f;
                    s1.w = (c1+1 <= qi2) ? s1.w : -1e30f;
                }
                pa[ntp][0] = h2ex2(pack_h2(s0.x, s0.y));
                pa[ntp][1] = h2ex2(pack_h2(s0.z, s0.w));
                pa[ntp][2] = h2ex2(pack_h2(s1.x, s1.y));
                pa[ntp][3] = h2ex2(pack_h2(s1.z, s1.w));
            }
        }
        pdead = dead;
    }

    // ---- epilogue: final PV + normalize ----
    if (!pdead) {
        const int pb = (nkv - 1) & 3;
        const uint32_t vbase = s2u(VsB[pb] + brow*AROWB + bcB);
        #pragma unroll
        for (int kc = 0; kc < 4; kc++) {
            #pragma unroll
            for (int ntp = 0; ntp < 4; ntp++) {
                uint32_t b0, b1, b2, b3;
                ldsm4(b0, b1, b2, b3, vbase + (uint32_t)(ntp*16*AROWB + kc*32));
                mma16(oacc[2*ntp  ], pa[kc][0], pa[kc][1], pa[kc][2], pa[kc][3], b0, b1);
                mma16(oacc[2*ntp+1], pa[kc][0], pa[kc][1], pa[kc][2], pa[kc][3], b2, b3);
            }
            mma16(osum, pa[kc][0], pa[kc][1], pa[kc][2], pa[kc][3], ONE2, ONE2);
        }
    }

    float il0 = 1.f / osum.x, il1 = 1.f / osum.z;
    const size_t r1off = base + (size_t)qi1 * D_MODEL;
    const size_t r2off = base + (size_t)qi2 * D_MODEL;
    #pragma unroll
    for (int nt = 0; nt < 8; nt++) {
        int col = nt*8 + 2*t;
        *(__half2*)&g_Attn[r1off + col] =
            __floats2half2_rn(oacc[nt].x*il0, oacc[nt].y*il0);
        *(__half2*)&g_Attn[r2off + col] =
            __floats2half2_rn(oacc[nt].z*il1, oacc[nt].w*il1);
    }
}

// ---------------- launch ----------------------------------------------------
extern "C" void kernel_launch(void* const* d_in, const int* in_sizes, int n_in,
                              void* d_out, int out_size)
{
    (void)in_sizes; (void)n_in; (void)out_size;
    const float* x   = (const float*)d_in[0];
    const int*   pos = (const int*)  d_in[1];
    const float* Wq  = (const float*)d_in[2];
    const float* bq  = (const float*)d_in[3];
    const float* Wk  = (const float*)d_in[4];
    const float* bk  = (const float*)d_in[5];
    // d_in[6], d_in[7] (Wv, bv) unused: reference computes V with Wq/bq
    const float* Wo  = (const float*)d_in[8];
    const float* bo  = (const float*)d_in[9];
    float* out = (float*)d_out;

    cudaFuncSetAttribute(attn_kernel,
                         cudaFuncAttributeMaxDynamicSharedMemorySize, ATT_SMEM_BYTES);

    rope_table_kernel<<<TT, 32>>>(pos);

    f2h_all_kernel<<<(NALL8 + 255)/256, 256>>>(
        (const float4*)x, (const float4*)Wq,
        (const float4*)Wk, (const float4*)Wo);

    dim3 gq(D_MODEL/128, MTOT/128, 2);
    qk_gemm_kernel<<<gq, 256>>>(bq, bk);

    dim3 ga(TT/128, NHEADS, BB);
    attn_kernel<<<ga, 256, ATT_SMEM_BYTES>>>();

    dim3 go(D_MODEL/128, MTOT/128, 1);
    o_gemm_kernel<<<go, 256>>>(bo, out);
}

// round 15
// speedup vs baseline: 1.2222x; 1.1717x over previous
#include <cuda_runtime.h>
#include <cuda_fp16.h>
#include <math.h>
#include <stdint.h>

#define D_MODEL 1024
#define NHEADS  16
#define DK      64
#define BB      2
#define TT      2048
#define MTOT    (BB*TT)   // 4096 rows

// ---------------- scratch (static device arrays; no allocation allowed) ----
__device__ __half g_Qr[MTOT*D_MODEL];    // RoPE'd Q, pre-scaled by 0.125*log2(e)
__device__ __half g_Kr[MTOT*D_MODEL];    // RoPE'd K (fp16)
__device__ __half g_Vt[MTOT*D_MODEL];    // V transposed [b,h,d,t] (fp16)
__device__ __half g_Attn[MTOT*D_MODEL];  // attention output (fp16)
__device__ __half g_Xh[MTOT*D_MODEL];    // input x (fp16)
__device__ __half g_Wqh[D_MODEL*D_MODEL];
__device__ __half g_Wkh[D_MODEL*D_MODEL];
__device__ __half g_Woh[D_MODEL*D_MODEL];
__device__ float  g_cos[TT*32];
__device__ float  g_sin[TT*32];

#define EXP_SCALE 0.180336880111120405f   // 0.125 * log2(e), folded into Q

// ---------------- helpers ---------------------------------------------------
__device__ __forceinline__ void mma16(float4& c,
    uint32_t a0, uint32_t a1, uint32_t a2, uint32_t a3,
    uint32_t b0, uint32_t b1)
{
    asm volatile(
        "mma.sync.aligned.m16n8k16.row.col.f32.f16.f16.f32 "
        "{%0,%1,%2,%3}, {%4,%5,%6,%7}, {%8,%9}, {%0,%1,%2,%3};\n"
        : "+f"(c.x), "+f"(c.y), "+f"(c.z), "+f"(c.w)
        : "r"(a0), "r"(a1), "r"(a2), "r"(a3), "r"(b0), "r"(b1));
}

__device__ __forceinline__ void ldsm4(uint32_t& r0, uint32_t& r1,
                                      uint32_t& r2, uint32_t& r3, uint32_t addr)
{
    asm volatile("ldmatrix.sync.aligned.m8n8.x4.shared.b16 {%0,%1,%2,%3}, [%4];"
                 : "=r"(r0), "=r"(r1), "=r"(r2), "=r"(r3) : "r"(addr));
}

__device__ __forceinline__ uint32_t s2u(const void* p)
{
    return (uint32_t)__cvta_generic_to_shared(p);
}

__device__ __forceinline__ void cpa16(uint32_t dst, const void* src)
{
    asm volatile("cp.async.cg.shared.global [%0], [%1], 16;" :: "r"(dst), "l"(src));
}
#define CP_COMMIT() asm volatile("cp.async.commit_group;" ::: "memory")
#define CP_WAIT0()  asm volatile("cp.async.wait_group 0;" ::: "memory")
#define CP_WAIT1()  asm volatile("cp.async.wait_group 1;" ::: "memory")

__device__ __forceinline__ uint32_t pack_h2(float x, float y)
{
    __half2 h = __floats2half2_rn(x, y);
    return *(uint32_t*)&h;
}

__device__ __forceinline__ uint32_t h2ex2(uint32_t u)
{
    uint32_t r;
    asm("ex2.approx.f16x2 %0, %1;" : "=r"(r) : "r"(u));
    return r;
}

// ---------------- prepass: fused f32 -> f16 for x, Wq, Wk, Wo ----------------
#define NX8 (MTOT*D_MODEL/8)       // 524288
#define NW8 (D_MODEL*D_MODEL/8)    // 131072
#define NALL8 (NX8 + 3*NW8)        // 917504

__global__ void f2h_all_kernel(const float4* __restrict__ x,
                               const float4* __restrict__ wq,
                               const float4* __restrict__ wk,
                               const float4* __restrict__ wo)
{
    int i = blockIdx.x * blockDim.x + threadIdx.x;
    if (i >= NALL8) return;
    const float4* src;
    uint4* dst;
    int j;
    if (i < NX8)               { src = x;  dst = (uint4*)g_Xh;  j = i; }
    else if (i < NX8 + NW8)    { src = wq; dst = (uint4*)g_Wqh; j = i - NX8; }
    else if (i < NX8 + 2*NW8)  { src = wk; dst = (uint4*)g_Wkh; j = i - NX8 - NW8; }
    else                       { src = wo; dst = (uint4*)g_Woh; j = i - NX8 - 2*NW8; }
    float4 a = src[2*j], b = src[2*j+1];
    union { uint4 u; __half2 h[4]; } p;
    p.h[0] = __floats2half2_rn(a.x, a.y);
    p.h[1] = __floats2half2_rn(a.z, a.w);
    p.h[2] = __floats2half2_rn(b.x, b.y);
    p.h[3] = __floats2half2_rn(b.z, b.w);
    dst[j] = p.u;
}

// ---------------- RoPE table ------------------------------------------------
__global__ void rope_table_kernel(const int* __restrict__ pos)
{
    int t = blockIdx.x;
    int i = threadIdx.x;          // 0..31
    double inv = pow(10000.0, -((double)(2*i) / 64.0));
    float ang = (float)pos[t] * (float)inv;
    g_cos[t*32 + i] = cosf(ang);
    g_sin[t*32 + i] = sinf(ang);
}

// ---------------- FP16 mma GEMM core (2-stage, static smem) ------------------
#define GROWB 80                    // bytes per smem row
#define GTILEB (128*GROWB)          // 10240 B per tile buffer
#define GEMM_SMEM_BYTES (4*GTILEB)  // A0,B0,A1,B1 = 40960 B (static)

struct GemmAcc { float4 acc[4][4]; };

__device__ __forceinline__ void gemm_core(
    const __half* __restrict__ Xrow,
    const __half* __restrict__ Wrow,
    char* gsm, GemmAcc& R, int tid, int wm, int wn, int lane)
{
    char* A0 = gsm;
    char* B0 = gsm + GTILEB;
    char* A1 = gsm + 2*GTILEB;
    char* B1 = gsm + 3*GTILEB;

    #pragma unroll
    for (int i = 0; i < 4; i++)
        #pragma unroll
        for (int j = 0; j < 4; j++) R.acc[i][j] = make_float4(0.f,0.f,0.f,0.f);

    const int row  = tid >> 1;
    const int hofB = (tid & 1) * 32;

    const int arow = lane & 15;
    const int acB  = (lane >> 4) * 16;
    const int brow = ((lane >> 4) << 3) + (lane & 7);
    const int bcB  = ((lane >> 3) & 1) * 16;

    #pragma unroll
    for (int c = 0; c < 2; c++) {
        cpa16(s2u(A0 + row*GROWB + hofB + c*16), Xrow + c*8);
        cpa16(s2u(B0 + row*GROWB + hofB + c*16), Wrow + c*8);
    }
    CP_COMMIT();

    for (int k0 = 0; k0 < D_MODEL; k0 += 32) {
        CP_WAIT0();
        __syncthreads();
        char* Ac = (k0 & 32) ? A1 : A0;
        char* Bc = (k0 & 32) ? B1 : B0;
        if (k0 + 32 < D_MODEL) {
            char* An = (k0 & 32) ? A0 : A1;
            char* Bn = (k0 & 32) ? B0 : B1;
            #pragma unroll
            for (int c = 0; c < 2; c++) {
                cpa16(s2u(An + row*GROWB + hofB + c*16), Xrow + k0 + 32 + c*8);
                cpa16(s2u(Bn + row*GROWB + hofB + c*16), Wrow + k0 + 32 + c*8);
            }
            CP_COMMIT();
        }
        uint32_t abase = s2u(Ac + (wm*64 + arow)*GROWB + acB);
        uint32_t bbase = s2u(Bc + (wn*32 + brow)*GROWB + bcB);
        #pragma unroll
        for (int ks = 0; ks < 2; ks++) {
            uint32_t af[4][4];
            #pragma unroll
            for (int mt = 0; mt < 4; mt++)
                ldsm4(af[mt][0], af[mt][1], af[mt][2], af[mt][3],
                      abase + (uint32_t)(mt*16*GROWB + ks*32));
            #pragma unroll
            for (int ntp = 0; ntp < 2; ntp++) {
                uint32_t b0, b1, b2, b3;
                ldsm4(b0, b1, b2, b3, bbase + (uint32_t)(ntp*16*GROWB + ks*32));
                #pragma unroll
                for (int mt = 0; mt < 4; mt++) {
                    mma16(R.acc[mt][2*ntp  ], af[mt][0],af[mt][1],af[mt][2],af[mt][3], b0, b1);
                    mma16(R.acc[mt][2*ntp+1], af[mt][0],af[mt][1],af[mt][2],af[mt][3], b2, b3);
                }
            }
        }
    }
}

// ---------------- Q/K projection + RoPE epilogue ----------------------------
__global__ __launch_bounds__(256) void qk_gemm_kernel(
    const float* __restrict__ bq, const float* __restrict__ bk)
{
    __shared__ __align__(16) char gsm[GEMM_SMEM_BYTES];
    const __half* W    = blockIdx.z ? g_Wkh : g_Wqh;
    const float*  bias = blockIdx.z ? bk : bq;

    const int tid = threadIdx.x, lane = tid & 31, warp = tid >> 5;
    const int wm = warp >> 2, wn = warp & 3;
    const int g = lane >> 2, t = lane & 3;
    const int m0 = blockIdx.y * 128, n0 = blockIdx.x * 128;
    const int row = tid >> 1, hoff = (tid & 1) * 16;

    GemmAcc R;
    gemm_core(g_Xh + (size_t)(m0 + row) * D_MODEL + hoff,
              W    + (size_t)(n0 + row) * D_MODEL + hoff,
              gsm, R, tid, wm, wn, lane);

    __half* outR = blockIdx.z ? g_Kr : g_Qr;
    const bool writeV = (blockIdx.z == 0);
    const float sc = writeV ? EXP_SCALE : 1.0f;   // fold softmax scale into Q

    #pragma unroll
    for (int mt = 0; mt < 4; mt++) {
        int r1 = m0 + wm*64 + mt*16 + g;
        int r2 = r1 + 8;
        int t1 = r1 & (TT-1), t2 = r2 & (TT-1);
        int b1i = r1 >> 11, b2i = r2 >> 11;
        #pragma unroll
        for (int nt = 0; nt < 4; nt++) {
            int n = n0 + wn*32 + nt*8 + 2*t;
            float b0v = bias[n], b1v = bias[n+1];
            int fi = (n & 63) >> 1;
            float4 c = R.acc[mt][nt];
            float y1 = c.x + b0v, y2 = c.y + b1v;
            float z1 = c.z + b0v, z2 = c.w + b1v;
            if (writeV) {
                int h = n >> 6, d = n & 63;
                size_t vb1 = ((size_t)(b1i*NHEADS + h)*DK + d)*TT;
                size_t vb2 = ((size_t)(b2i*NHEADS + h)*DK + d)*TT;
                g_Vt[vb1 + t1]      = __float2half_rn(y1);
                g_Vt[vb1 + TT + t1] = __float2half_rn(y2);
                g_Vt[vb2 + t2]      = __float2half_rn(z1);
                g_Vt[vb2 + TT + t2] = __float2half_rn(z2);
            }
            float c1 = g_cos[t1*32+fi], s1 = g_sin[t1*32+fi];
            float c2 = g_cos[t2*32+fi], s2 = g_sin[t2*32+fi];
            *(__half2*)&outR[(size_t)r1*D_MODEL + n] =
                __floats2half2_rn((y1*c1 - y2*s1)*sc, (y1*s1 + y2*c1)*sc);
            *(__half2*)&outR[(size_t)r2*D_MODEL + n] =
                __floats2half2_rn((z1*c2 - z2*s2)*sc, (z1*s2 + z2*c2)*sc);
        }
    }
}

// ---------------- output projection -----------------------------------------
__global__ __launch_bounds__(256) void o_gemm_kernel(
    const float* __restrict__ bias, float* __restrict__ Y)
{
    __shared__ __align__(16) char gsm[GEMM_SMEM_BYTES];
    const int tid = threadIdx.x, lane = tid & 31, warp = tid >> 5;
    const int wm = warp >> 2, wn = warp & 3;
    const int g = lane >> 2, t = lane & 3;
    const int m0 = blockIdx.y * 128, n0 = blockIdx.x * 128;
    const int row = tid >> 1, hoff = (tid & 1) * 16;

    GemmAcc R;
    gemm_core(g_Attn + (size_t)(m0 + row) * D_MODEL + hoff,
              g_Woh  + (size_t)(n0 + row) * D_MODEL + hoff,
              gsm, R, tid, wm, wn, lane);

    #pragma unroll
    for (int mt = 0; mt < 4; mt++) {
        int r1 = m0 + wm*64 + mt*16 + g;
        int r2 = r1 + 8;
        #pragma unroll
        for (int nt = 0; nt < 4; nt++) {
            int n = n0 + wn*32 + nt*8 + 2*t;
            float b0v = bias[n], b1v = bias[n+1];
            float4 c = R.acc[mt][nt];
            *(float2*)&Y[(size_t)r1*D_MODEL + n] = make_float2(c.x + b0v, c.y + b1v);
            *(float2*)&Y[(size_t)r2*D_MODEL + n] = make_float2(c.z + b0v, c.w + b1v);
        }
    }
}

// ---------------- flash attention (4-buffer ring, wide-ILP S, reg P) --------
// 1-D grid with global LPT order: biggest causal tiles dispatched first.
// S computed kc-outer/ntp-inner into sacc[8] -> 8 independent mma chains.
#define AROWB 144
#define KTILEB (64*AROWB)                       // 9216 B
#define ATT_SMEM_BYTES (8*KTILEB)               // 4 x (K,V) = 73728 B
#define ONE2 0x3C003C00u                        // half2(1.0, 1.0)
#define NQT (TT/128)                            // 16 q-tiles

__global__ __launch_bounds__(256) void attn_kernel()
{
    extern __shared__ char asm_[];
    char* KsB[4] = { asm_,            asm_ + 2*KTILEB,
                     asm_ + 4*KTILEB, asm_ + 6*KTILEB };
    char* VsB[4] = { asm_ + KTILEB,   asm_ + 3*KTILEB,
                     asm_ + 5*KTILEB, asm_ + 7*KTILEB };

    const int tid = threadIdx.x, lane = tid & 31, warp = tid >> 5;
    const int g = lane >> 2, t = lane & 3;
    // global LPT decode: qrank 0 = largest tile, across all (h,b)
    const int qrank = blockIdx.x >> 5;
    const int hb = blockIdx.x & 31;
    const int h = hb & 15, b = hb >> 4;
    const int qbase = (NQT - 1 - qrank) * 128;
    const size_t base = (size_t)b * TT * D_MODEL + h * DK;
    const __half* Qb  = g_Qr + base;
    const __half* Kb  = g_Kr + base;
    const __half* Vtb = g_Vt + (size_t)(b*NHEADS + h) * DK * TT;

    const int srj  = tid >> 2;
    const int hoff = (tid & 3) * 16;
    const __half* ksrc = Kb  + (size_t)srj * D_MODEL + hoff;
    const __half* vsrc = Vtb + (size_t)srj * TT + hoff;

    const int brow = ((lane >> 4) << 3) + (lane & 7);
    const int bcB  = ((lane >> 3) & 1) * 16;

    // Q fragments in registers
    uint32_t qa[4][4];
    {
        const __half* q1 = Qb + (size_t)(qbase + warp*16 + g) * D_MODEL;
        const __half* q2 = q1 + (size_t)8 * D_MODEL;
        #pragma unroll
        for (int kc = 0; kc < 4; kc++) {
            qa[kc][0] = *(const uint32_t*)(q1 + kc*16 + 2*t);
            qa[kc][1] = *(const uint32_t*)(q2 + kc*16 + 2*t);
            qa[kc][2] = *(const uint32_t*)(q1 + kc*16 + 2*t + 8);
            qa[kc][3] = *(const uint32_t*)(q2 + kc*16 + 2*t + 8);
        }
    }

    float4 oacc[8];
    #pragma unroll
    for (int nt = 0; nt < 8; nt++) oacc[nt] = make_float4(0.f,0.f,0.f,0.f);
    float4 osum = make_float4(0.f,0.f,0.f,0.f);   // row sums via ones mma
    uint32_t pa[4][4];                            // P(jt-1) fragments (fp16)

    const int qi1 = qbase + warp*16 + g;
    const int qi2 = qi1 + 8;
    const int wrow0 = qbase + warp*16;            // warp's min q row
    const int nkv = (qbase + 128) / 64;           // >= 2 always
    bool pdead = true;                            // P(jt-1) absent

    auto stageKV = [&](int jtile, int buf) {
        const size_t koff = (size_t)(jtile*64) * D_MODEL;
        const int    voff = jtile*64;
        #pragma unroll
        for (int c = 0; c < 2; c++) {
            cpa16(s2u(KsB[buf] + srj*AROWB + hoff*2 + c*16), ksrc + koff + c*8);
            cpa16(s2u(VsB[buf] + srj*AROWB + hoff*2 + c*16), vsrc + voff + c*8);
        }
    };

    stageKV(0, 0); CP_COMMIT();
    stageKV(1, 1); CP_COMMIT();

    for (int jt = 0; jt < nkv; jt++) {
        const int j0 = jt * 64;
        CP_WAIT1();
        __syncthreads();          // K/V(jt) staged & visible; iter jt-1 done
        const int cb = jt & 3;
        const int pb = (jt + 3) & 3;

        // ---- PV(jt-1): register P against V[pb] ----
        if (!pdead) {
            const uint32_t vbase = s2u(VsB[pb] + brow*AROWB + bcB);
            #pragma unroll
            for (int kc = 0; kc < 4; kc++) {
                #pragma unroll
                for (int ntp = 0; ntp < 4; ntp++) {
                    uint32_t b0, b1, b2, b3;
                    ldsm4(b0, b1, b2, b3, vbase + (uint32_t)(ntp*16*AROWB + kc*32));
                    mma16(oacc[2*ntp  ], pa[kc][0], pa[kc][1], pa[kc][2], pa[kc][3], b0, b1);
                    mma16(oacc[2*ntp+1], pa[kc][0], pa[kc][1], pa[kc][2], pa[kc][3], b2, b3);
                }
                mma16(osum, pa[kc][0], pa[kc][1], pa[kc][2], pa[kc][3], ONE2, ONE2);
            }
        }

        // ---- prefetch K/V(jt+2) into (jt+2)&3 ----
        if (jt + 2 < nkv) stageKV(jt + 2, (jt + 2) & 3);
        CP_COMMIT();              // may be empty near the end

        // ---- S(jt): kc-outer / ntp-inner -> 8 independent chains ----------
        const bool dead = (j0 > wrow0 + 15);   // warp-uniform
        if (!dead) {
            const bool full = (j0 + 63 <= wrow0);
            const uint32_t kbase = s2u(KsB[cb] + brow*AROWB + bcB);
            float4 sacc[8];
            #pragma unroll
            for (int nt = 0; nt < 8; nt++) sacc[nt] = make_float4(0.f,0.f,0.f,0.f);
            #pragma unroll
            for (int kc = 0; kc < 4; kc++) {
                #pragma unroll
                for (int ntp = 0; ntp < 4; ntp++) {
                    uint32_t b0, b1, b2, b3;
                    ldsm4(b0, b1, b2, b3, kbase + (uint32_t)(ntp*16*AROWB + kc*32));
                    mma16(sacc[2*ntp  ], qa[kc][0], qa[kc][1], qa[kc][2], qa[kc][3], b0, b1);
                    mma16(sacc[2*ntp+1], qa[kc][0], qa[kc][1], qa[kc][2], qa[kc][3], b2, b3);
                }
            }
            // mask + f16x2 exp -> register P (A-fragment layout)
            #pragma unroll
            for (int ntp = 0; ntp < 4; ntp++) {
                float4 s0 = sacc[2*ntp], s1 = sacc[2*ntp+1];
                if (!full) {
                    int c0 = j0 + ntp*16 + 2*t;
                    int c1 = c0 + 8;
                    s0.x = (c0   <= qi1) ? s0.x : -1e30f;
                    s0.y = (c0+1 <= qi1) ? s0.y : -1e30f;
                    s0.z = (c0   <= qi2) ? s0.z : -1e30f;
                    s0.w = (c0+1 <= qi2) ? s0.w : -1e30f;
                    s1.x = (c1   <= qi1) ? s1.x : -1e30f;
                    s1.y = (c1+1 <= qi1) ? s1.y : -1e30f;
                    s1.z = (c1   <= qi2) ? s1.z : -1e30f;
                    s1.w = (c1+1 <= qi2) ? s1.w : -1e30f;
                }
                pa[ntp][0] = h2ex2(pack_h2(s0.x, s0.y));
                pa[ntp][1] = h2ex2(pack_h2(s0.z, s0.w));
                pa[ntp][2] = h2ex2(pack_h2(s1.x, s1.y));
                pa[ntp][3] = h2ex2(pack_h2(s1.z, s1.w));
            }
        }
        pdead = dead;
    }

    // ---- epilogue: final PV + normalize ----
    if (!pdead) {
        const int pb = (nkv - 1) & 3;
        const uint32_t vbase = s2u(VsB[pb] + brow*AROWB + bcB);
        #pragma unroll
        for (int kc = 0; kc < 4; kc++) {
            #pragma unroll
            for (int ntp = 0; ntp < 4; ntp++) {
                uint32_t b0, b1, b2, b3;
                ldsm4(b0, b1, b2, b3, vbase + (uint32_t)(ntp*16*AROWB + kc*32));
                mma16(oacc[2*ntp  ], pa[kc][0], pa[kc][1], pa[kc][2], pa[kc][3], b0, b1);
                mma16(oacc[2*ntp+1], pa[kc][0], pa[kc][1], pa[kc][2], pa[kc][3], b2, b3);
            }
            mma16(osum, pa[kc][0], pa[kc][1], pa[kc][2], pa[kc][3], ONE2, ONE2);
        }
    }

    float il0 = 1.f / osum.x, il1 = 1.f / osum.z;
    const size_t r1off = base + (size_t)qi1 * D_MODEL;
    const size_t r2off = base + (size_t)qi2 * D_MODEL;
    #pragma unroll
    for (int nt = 0; nt < 8; nt++) {
        int col = nt*8 + 2*t;
        *(__half2*)&g_Attn[r1off + col] =
            __floats2half2_rn(oacc[nt].x*il0, oacc[nt].y*il0);
        *(__half2*)&g_Attn[r2off + col] =
            __floats2half2_rn(oacc[nt].z*il1, oacc[nt].w*il1);
    }
}

// ---------------- launch ----------------------------------------------------
extern "C" void kernel_launch(void* const* d_in, const int* in_sizes, int n_in,
                              void* d_out, int out_size)
{
    (void)in_sizes; (void)n_in; (void)out_size;
    const float* x   = (const float*)d_in[0];
    const int*   pos = (const int*)  d_in[1];
    const float* Wq  = (const float*)d_in[2];
    const float* bq  = (const float*)d_in[3];
    const float* Wk  = (const float*)d_in[4];
    const float* bk  = (const float*)d_in[5];
    // d_in[6], d_in[7] (Wv, bv) unused: reference computes V with Wq/bq
    const float* Wo  = (const float*)d_in[8];
    const float* bo  = (const float*)d_in[9];
    float* out = (float*)d_out;

    cudaFuncSetAttribute(attn_kernel,
                         cudaFuncAttributeMaxDynamicSharedMemorySize, ATT_SMEM_BYTES);

    rope_table_kernel<<<TT, 32>>>(pos);

    f2h_all_kernel<<<(NALL8 + 255)/256, 256>>>(
        (const float4*)x, (const float4*)Wq,
        (const float4*)Wk, (const float4*)Wo);

    dim3 gq(D_MODEL/128, MTOT/128, 2);
    qk_gemm_kernel<<<gq, 256>>>(bq, bk);

    attn_kernel<<<NQT*NHEADS*BB, 256, ATT_SMEM_BYTES>>>();

    dim3 go(D_MODEL/128, MTOT/128, 1);
    o_gemm_kernel<<<go, 256>>>(bo, out);
}